// round 6
// baseline (speedup 1.0000x reference)
#include <cuda_runtime.h>
#include <cstdint>
#include <cstddef>

// ---------------- problem constants ----------------
constexpr int N_NODES = 100000;
constexpr int IN_C    = 256;
constexpr int HID_C   = 128;
constexpr int OUT_C   = 64;
constexpr int N_EDGES = 1600000;
constexpr int N_LBL   = 200000;

// ---------------- scratch (device globals) ----------------------------------
__device__ __align__(16) int   g_deg   [N_NODES];
__device__ __align__(16) int   g_rowptr[N_NODES + 1];
__device__ __align__(16) int   g_cursor[N_NODES];
__device__ __align__(16) int   g_col   [N_EDGES];
__device__ __align__(16) float g_dinv  [N_NODES];
__device__ __align__(16) float g_bufA[(size_t)N_NODES * HID_C]; // h0 = x@W1 (unscaled)
__device__ __align__(16) float g_h   [(size_t)N_NODES * HID_C]; // h (post layer 1)
__device__ __align__(16) float g_z0s [(size_t)N_NODES * OUT_C]; // h@W2 (unscaled)
__device__ __align__(16) float g_z   [(size_t)N_NODES * OUT_C]; // final node embeddings

// ---------------- CSR build --------------------------------------------------
__global__ void zero_deg_kernel() {
    const int i = blockIdx.x * blockDim.x + threadIdx.x;
    if (i < N_NODES) g_deg[i] = 0;
}

__global__ void deg_count_kernel(const int* __restrict__ ei) {
    const int idx    = blockIdx.x * blockDim.x + threadIdx.x;
    const int stride = gridDim.x * blockDim.x;
    for (int e = idx; e < N_EDGES; e += stride)
        atomicAdd(&g_deg[__ldg(&ei[N_EDGES + e])], 1);
}

constexpr int SCAN_T  = 1024;
constexpr int SCAN_CH = (N_NODES + SCAN_T - 1) / SCAN_T;   // 98

__global__ void rowptr_kernel() {
    __shared__ int part[SCAN_T];
    const int t    = threadIdx.x;
    const int base = t * SCAN_CH;
    int sum = 0;
    for (int i = 0; i < SCAN_CH; i++) {
        int idx = base + i;
        if (idx < N_NODES) sum += g_deg[idx];
    }
    part[t] = sum;
    __syncthreads();
#pragma unroll
    for (int off = 1; off < SCAN_T; off <<= 1) {
        int v = (t >= off) ? part[t - off] : 0;
        __syncthreads();
        part[t] += v;
        __syncthreads();
    }
    int run = part[t] - sum;
    for (int i = 0; i < SCAN_CH; i++) {
        int idx = base + i;
        if (idx < N_NODES) {
            g_rowptr[idx] = run;
            g_cursor[idx] = run;
            run += g_deg[idx];
        }
    }
    if (t == 0) g_rowptr[N_NODES] = part[SCAN_T - 1];
}

__global__ void fill_kernel(const int* __restrict__ ei) {
    const int idx    = blockIdx.x * blockDim.x + threadIdx.x;
    const int stride = gridDim.x * blockDim.x;
    for (int e = idx; e < N_EDGES; e += stride) {
        int s = __ldg(&ei[e]);
        int d = __ldg(&ei[N_EDGES + e]);
        int pos = atomicAdd(&g_cursor[d], 1);
        g_col[pos] = s;
    }
}

__global__ void dinv_kernel() {
    const int i = blockIdx.x * blockDim.x + threadIdx.x;
    if (i < N_NODES) g_dinv[i] = rsqrtf((float)g_deg[i] + 1.0f);  // +1 self-loop
}

// ---------------- packed f32x2 helpers --------------------------------------
__device__ __forceinline__ void ffma2(unsigned long long& d,
                                      unsigned long long a,
                                      unsigned long long b) {
    asm("fma.rn.f32x2 %0, %1, %2, %0;" : "+l"(d) : "l"(a), "l"(b));
}
__device__ __forceinline__ unsigned long long splat2(float x) {
    unsigned long long r;
    unsigned u = __float_as_uint(x);
    asm("mov.b64 %0, {%1, %1};" : "=l"(r) : "r"(u));
    return r;
}
__device__ __forceinline__ float2 unpack2(unsigned long long v) {
    unsigned lo, hi;
    asm("mov.b64 {%0, %1}, %2;" : "=r"(lo), "=r"(hi) : "l"(v));
    return make_float2(__uint_as_float(lo), __uint_as_float(hi));
}

// ---------------- fp32 GEMM (no scaling): out = X @ W -----------------------
// BM=128, BK=16, 8x8 register tile, FFMA2 inner product.
template <int BN, int K>
__device__ __forceinline__ void gemm_core(const float* __restrict__ X,
                                          const float* __restrict__ W,
                                          float* __restrict__ out) {
    constexpr int BM = 128, BK = 16;
    constexpr int TX = BN / 8;
    constexpr int NT = 16 * TX;

    __shared__ float xs[BK][BM];
    __shared__ float ws[BK][BN];

    const int tid  = threadIdx.x;
    const int tx   = tid % TX;
    const int ty   = tid / TX;
    const int row0 = blockIdx.x * BM;

    unsigned long long acc2[8][4];
#pragma unroll
    for (int i = 0; i < 8; i++)
#pragma unroll
        for (int j = 0; j < 4; j++) acc2[i][j] = 0ull;   // bits of {0f,0f}

    for (int k0 = 0; k0 < K; k0 += BK) {
#pragma unroll
        for (int f = tid; f < BM * BK / 4; f += NT) {
            int r  = f >> 2;
            int kq = f & 3;
            int gr = row0 + r;
            if (gr > N_NODES - 1) gr = N_NODES - 1;   // clamp; dup row discarded
            float4 v = *reinterpret_cast<const float4*>(X + (size_t)gr * K + k0 + kq * 4);
            xs[kq * 4 + 0][r] = v.x;
            xs[kq * 4 + 1][r] = v.y;
            xs[kq * 4 + 2][r] = v.z;
            xs[kq * 4 + 3][r] = v.w;
        }
#pragma unroll
        for (int f = tid; f < BK * BN / 4; f += NT) {
            int kr = f / (BN / 4);
            int cq = f % (BN / 4);
            *reinterpret_cast<float4*>(&ws[kr][cq * 4]) =
                *reinterpret_cast<const float4*>(W + (size_t)(k0 + kr) * BN + cq * 4);
        }
        __syncthreads();

#pragma unroll
        for (int kk = 0; kk < BK; kk++) {
            float a[8];
            *reinterpret_cast<float4*>(a)     = *reinterpret_cast<const float4*>(&xs[kk][ty * 8]);
            *reinterpret_cast<float4*>(a + 4) = *reinterpret_cast<const float4*>(&xs[kk][ty * 8 + 4]);
            ulonglong2 b0 = *reinterpret_cast<const ulonglong2*>(&ws[kk][tx * 8]);
            ulonglong2 b1 = *reinterpret_cast<const ulonglong2*>(&ws[kk][tx * 8 + 4]);
#pragma unroll
            for (int i = 0; i < 8; i++) {
                unsigned long long as = splat2(a[i]);
                ffma2(acc2[i][0], as, b0.x);
                ffma2(acc2[i][1], as, b0.y);
                ffma2(acc2[i][2], as, b1.x);
                ffma2(acc2[i][3], as, b1.y);
            }
        }
        __syncthreads();
    }

#pragma unroll
    for (int i = 0; i < 8; i++) {
        int r = row0 + ty * 8 + i;
        if (r < N_NODES) {
            float2 p0 = unpack2(acc2[i][0]);
            float2 p1 = unpack2(acc2[i][1]);
            float2 p2 = unpack2(acc2[i][2]);
            float2 p3 = unpack2(acc2[i][3]);
            float4 v0 = make_float4(p0.x, p0.y, p1.x, p1.y);
            float4 v1 = make_float4(p2.x, p2.y, p3.x, p3.y);
            *reinterpret_cast<float4*>(out + (size_t)r * BN + tx * 8)     = v0;
            *reinterpret_cast<float4*>(out + (size_t)r * BN + tx * 8 + 4) = v1;
        }
    }
}

__global__ void __launch_bounds__(256) gemm1_kernel(const float* __restrict__ X,
                                                    const float* __restrict__ W) {
    gemm_core<HID_C, IN_C>(X, W, g_bufA);
}
__global__ void __launch_bounds__(128) gemm2_kernel(const float* __restrict__ W) {
    gemm_core<OUT_C, HID_C>(g_h, W, g_z0s);
}

// ---------------- CSR aggregation, layer 1 (128 feats, warp/node) -----------
// h[i] = relu(dinv[i] * (dinv[i]*h0[i] + sum_s dinv[s]*h0[s]) + b1)
__global__ void __launch_bounds__(256) agg128_kernel(const float* __restrict__ b1) {
    const int lane = threadIdx.x & 31;
    const int node = (blockIdx.x * blockDim.x + threadIdx.x) >> 5;
    if (node >= N_NODES) return;
    const int beg = g_rowptr[node];
    const int end = g_rowptr[node + 1];
    const float4* __restrict__ H = reinterpret_cast<const float4*>(g_bufA);

    const float wn = g_dinv[node];
    float4 sv = H[(size_t)node * 32 + lane];
    float4 acc;
    acc.x = wn * sv.x; acc.y = wn * sv.y; acc.z = wn * sv.z; acc.w = wn * sv.w;

    int j = beg;
    for (; j + 7 < end; j += 8) {
        int   s[8];
        float w[8];
#pragma unroll
        for (int t = 0; t < 8; t++) s[t] = __ldg(&g_col[j + t]);
#pragma unroll
        for (int t = 0; t < 8; t++) w[t] = __ldg(&g_dinv[s[t]]);
#pragma unroll
        for (int t = 0; t < 8; t++) {
            float4 v = H[(size_t)s[t] * 32 + lane];
            acc.x = fmaf(w[t], v.x, acc.x);
            acc.y = fmaf(w[t], v.y, acc.y);
            acc.z = fmaf(w[t], v.z, acc.z);
            acc.w = fmaf(w[t], v.w, acc.w);
        }
    }
    for (; j < end; j++) {
        int s = __ldg(&g_col[j]);
        float w = __ldg(&g_dinv[s]);
        float4 v = H[(size_t)s * 32 + lane];
        acc.x = fmaf(w, v.x, acc.x);
        acc.y = fmaf(w, v.y, acc.y);
        acc.z = fmaf(w, v.z, acc.z);
        acc.w = fmaf(w, v.w, acc.w);
    }
    const float4 b = reinterpret_cast<const float4*>(b1)[lane];
    float4 r;
    r.x = fmaxf(fmaf(wn, acc.x, b.x), 0.f);
    r.y = fmaxf(fmaf(wn, acc.y, b.y), 0.f);
    r.z = fmaxf(fmaf(wn, acc.z, b.z), 0.f);
    r.w = fmaxf(fmaf(wn, acc.w, b.w), 0.f);
    reinterpret_cast<float4*>(g_h)[(size_t)node * 32 + lane] = r;
}

// ---------------- CSR aggregation, layer 2 (64 feats, 16 thr/node) ----------
__global__ void __launch_bounds__(256) agg64_kernel(const float* __restrict__ b2) {
    const int t0   = blockIdx.x * blockDim.x + threadIdx.x;
    const int l    = t0 & 15;
    const int node = t0 >> 4;
    if (node >= N_NODES) return;
    const int beg = g_rowptr[node];
    const int end = g_rowptr[node + 1];
    const float4* __restrict__ Z = reinterpret_cast<const float4*>(g_z0s);

    const float wn = g_dinv[node];
    float4 sv = Z[(size_t)node * 16 + l];
    float4 acc;
    acc.x = wn * sv.x; acc.y = wn * sv.y; acc.z = wn * sv.z; acc.w = wn * sv.w;

    int j = beg;
    for (; j + 7 < end; j += 8) {
        int   s[8];
        float w[8];
#pragma unroll
        for (int t = 0; t < 8; t++) s[t] = __ldg(&g_col[j + t]);
#pragma unroll
        for (int t = 0; t < 8; t++) w[t] = __ldg(&g_dinv[s[t]]);
#pragma unroll
        for (int t = 0; t < 8; t++) {
            float4 v = Z[(size_t)s[t] * 16 + l];
            acc.x = fmaf(w[t], v.x, acc.x);
            acc.y = fmaf(w[t], v.y, acc.y);
            acc.z = fmaf(w[t], v.z, acc.z);
            acc.w = fmaf(w[t], v.w, acc.w);
        }
    }
    for (; j < end; j++) {
        int s = __ldg(&g_col[j]);
        float w = __ldg(&g_dinv[s]);
        float4 v = Z[(size_t)s * 16 + l];
        acc.x = fmaf(w, v.x, acc.x);
        acc.y = fmaf(w, v.y, acc.y);
        acc.z = fmaf(w, v.z, acc.z);
        acc.w = fmaf(w, v.w, acc.w);
    }
    const float4 b = reinterpret_cast<const float4*>(b2)[l];
    float4 r;
    r.x = fmaf(wn, acc.x, b.x);
    r.y = fmaf(wn, acc.y, b.y);
    r.z = fmaf(wn, acc.z, b.z);
    r.w = fmaf(wn, acc.w, b.w);
    reinterpret_cast<float4*>(g_z)[(size_t)node * 16 + l] = r;
}

// ---------------- final: out[e] = dot(z[src], z[dst]) over 64 dims ----------
__global__ void edge_dot_kernel(const int* __restrict__ eli,
                                float* __restrict__ out) {
    const int lane = threadIdx.x & 31;
    const int warp = (blockIdx.x * blockDim.x + threadIdx.x) >> 5;
    if (warp >= N_LBL) return;
    int s = __ldg(&eli[warp]);
    int d = __ldg(&eli[N_LBL + warp]);
    float2 a = *reinterpret_cast<const float2*>(&g_z[(size_t)s * OUT_C + lane * 2]);
    float2 b = *reinterpret_cast<const float2*>(&g_z[(size_t)d * OUT_C + lane * 2]);
    float p = a.x * b.x + a.y * b.y;
#pragma unroll
    for (int o = 16; o > 0; o >>= 1) p += __shfl_xor_sync(0xffffffffu, p, o);
    if (lane == 0) out[warp] = p;
}

// ---------------- launch ----------------------------------------------------
extern "C" void kernel_launch(void* const* d_in, const int* in_sizes, int n_in,
                              void* d_out, int out_size) {
    const float* x   = (const float*)d_in[0];
    const int*   ei  = (const int*)d_in[1];   // int32 (JAX x64 disabled)
    const int*   eli = (const int*)d_in[2];
    const float* W1  = (const float*)d_in[3];
    const float* b1  = (const float*)d_in[4];
    const float* W2  = (const float*)d_in[5];
    const float* b2  = (const float*)d_in[6];
    float*       out = (float*)d_out;

    // Side stream for CSR build, forked/joined via events so it works both
    // under graph capture and in the plain correctness call. kernel_launch is
    // invoked only a handful of times (capture replays don't re-run host
    // code), so creating these per call is cheap; we do not destroy them to
    // stay safe w.r.t. capture-forked stream teardown.
    cudaStream_t s2;
    cudaEvent_t  e0, e1;
    cudaStreamCreateWithFlags(&s2, cudaStreamNonBlocking);
    cudaEventCreateWithFlags(&e0, cudaEventDisableTiming);
    cudaEventCreateWithFlags(&e1, cudaEventDisableTiming);

    cudaEventRecord(e0, 0);
    cudaStreamWaitEvent(s2, e0, 0);
    // CSR build chain on s2 (independent of gemm1)
    zero_deg_kernel<<<(N_NODES + 255) / 256, 256, 0, s2>>>();
    deg_count_kernel<<<2048, 256, 0, s2>>>(ei);
    rowptr_kernel<<<1, SCAN_T, 0, s2>>>();
    fill_kernel<<<2048, 256, 0, s2>>>(ei);
    dinv_kernel<<<(N_NODES + 255) / 256, 256, 0, s2>>>();
    cudaEventRecord(e1, s2);

    // gemm1 on the main stream, concurrent with CSR build
    gemm1_kernel<<<(N_NODES + 127) / 128, 256>>>(x, W1);
    cudaStreamWaitEvent(0, e1, 0);   // join before aggregation

    agg128_kernel<<<(N_NODES * 32 + 255) / 256, 256>>>(b1);
    gemm2_kernel<<<(N_NODES + 127) / 128, 128>>>(W2);
    agg64_kernel<<<(N_NODES * 16 + 255) / 256, 256>>>(b2);
    edge_dot_kernel<<<(N_LBL * 32 + 255) / 256, 256>>>(eli, out);
}

// round 7
// speedup vs baseline: 1.4980x; 1.4980x over previous
#include <cuda_runtime.h>
#include <cstdint>
#include <cstddef>

// ---------------- problem constants ----------------
constexpr int N_NODES = 100000;
constexpr int IN_C    = 256;
constexpr int HID_C   = 128;
constexpr int OUT_C   = 64;
constexpr int N_EDGES = 1600000;
constexpr int N_LBL   = 200000;

// ---------------- scratch (device globals) ----------------------------------
__device__ __align__(16) int   g_deg   [N_NODES];
__device__ __align__(16) int   g_rowptr[N_NODES + 1];
__device__ __align__(16) int   g_cursor[N_NODES];
__device__ __align__(16) int   g_col   [N_EDGES];
__device__ __align__(16) float g_dinv  [N_NODES];
__device__ __align__(16) float g_bufA[(size_t)N_NODES * HID_C]; // h0 = x@W1 (unscaled)
__device__ __align__(16) float g_h   [(size_t)N_NODES * HID_C]; // h (post layer 1)
__device__ __align__(16) float g_z0s [(size_t)N_NODES * OUT_C]; // h@W2 (unscaled)
__device__ __align__(16) float g_z   [(size_t)N_NODES * OUT_C]; // final node embeddings

// ---------------- CSR build --------------------------------------------------
__global__ void zero_deg_kernel() {
    const int i = blockIdx.x * blockDim.x + threadIdx.x;
    if (i < N_NODES) g_deg[i] = 0;
}

__global__ void deg_count_kernel(const int* __restrict__ ei) {
    const int idx    = blockIdx.x * blockDim.x + threadIdx.x;
    const int stride = gridDim.x * blockDim.x;
    for (int e = idx; e < N_EDGES; e += stride)
        atomicAdd(&g_deg[__ldg(&ei[N_EDGES + e])], 1);
}

constexpr int SCAN_T  = 1024;
constexpr int SCAN_CH = (N_NODES + SCAN_T - 1) / SCAN_T;   // 98

__global__ void rowptr_kernel() {
    __shared__ int part[SCAN_T];
    const int t    = threadIdx.x;
    const int base = t * SCAN_CH;
    int sum = 0;
    for (int i = 0; i < SCAN_CH; i++) {
        int idx = base + i;
        if (idx < N_NODES) sum += g_deg[idx];
    }
    part[t] = sum;
    __syncthreads();
#pragma unroll
    for (int off = 1; off < SCAN_T; off <<= 1) {
        int v = (t >= off) ? part[t - off] : 0;
        __syncthreads();
        part[t] += v;
        __syncthreads();
    }
    int run = part[t] - sum;
    for (int i = 0; i < SCAN_CH; i++) {
        int idx = base + i;
        if (idx < N_NODES) {
            g_rowptr[idx] = run;
            g_cursor[idx] = run;
            run += g_deg[idx];
        }
    }
    if (t == 0) g_rowptr[N_NODES] = part[SCAN_T - 1];
}

__global__ void fill_kernel(const int* __restrict__ ei) {
    const int idx    = blockIdx.x * blockDim.x + threadIdx.x;
    const int stride = gridDim.x * blockDim.x;
    for (int e = idx; e < N_EDGES; e += stride) {
        int s = __ldg(&ei[e]);
        int d = __ldg(&ei[N_EDGES + e]);
        int pos = atomicAdd(&g_cursor[d], 1);
        g_col[pos] = s;
    }
}

__global__ void dinv_kernel() {
    const int i = blockIdx.x * blockDim.x + threadIdx.x;
    if (i < N_NODES) g_dinv[i] = rsqrtf((float)g_deg[i] + 1.0f);  // +1 self-loop
}

// ---------------- fp32 GEMM (no scaling): out = X @ W -----------------------
// BM=128, BK=16, 8x8 register tile, scalar FFMA (known-good round-3/5 core).
template <int BN, int K>
__device__ __forceinline__ void gemm_core(const float* __restrict__ X,
                                          const float* __restrict__ W,
                                          float* __restrict__ out) {
    constexpr int BM = 128, BK = 16;
    constexpr int TX = BN / 8;
    constexpr int NT = 16 * TX;

    __shared__ float xs[BK][BM];
    __shared__ float ws[BK][BN];

    const int tid  = threadIdx.x;
    const int tx   = tid % TX;
    const int ty   = tid / TX;
    const int row0 = blockIdx.x * BM;

    float acc[8][8];
#pragma unroll
    for (int i = 0; i < 8; i++)
#pragma unroll
        for (int j = 0; j < 8; j++) acc[i][j] = 0.f;

    for (int k0 = 0; k0 < K; k0 += BK) {
#pragma unroll
        for (int f = tid; f < BM * BK / 4; f += NT) {
            int r  = f >> 2;
            int kq = f & 3;
            int gr = row0 + r;
            if (gr > N_NODES - 1) gr = N_NODES - 1;   // clamp; dup row discarded
            float4 v = *reinterpret_cast<const float4*>(X + (size_t)gr * K + k0 + kq * 4);
            xs[kq * 4 + 0][r] = v.x;
            xs[kq * 4 + 1][r] = v.y;
            xs[kq * 4 + 2][r] = v.z;
            xs[kq * 4 + 3][r] = v.w;
        }
#pragma unroll
        for (int f = tid; f < BK * BN / 4; f += NT) {
            int kr = f / (BN / 4);
            int cq = f % (BN / 4);
            *reinterpret_cast<float4*>(&ws[kr][cq * 4]) =
                *reinterpret_cast<const float4*>(W + (size_t)(k0 + kr) * BN + cq * 4);
        }
        __syncthreads();

#pragma unroll
        for (int kk = 0; kk < BK; kk++) {
            float a[8], b[8];
            *reinterpret_cast<float4*>(a)     = *reinterpret_cast<const float4*>(&xs[kk][ty * 8]);
            *reinterpret_cast<float4*>(a + 4) = *reinterpret_cast<const float4*>(&xs[kk][ty * 8 + 4]);
            *reinterpret_cast<float4*>(b)     = *reinterpret_cast<const float4*>(&ws[kk][tx * 8]);
            *reinterpret_cast<float4*>(b + 4) = *reinterpret_cast<const float4*>(&ws[kk][tx * 8 + 4]);
#pragma unroll
            for (int i = 0; i < 8; i++)
#pragma unroll
                for (int j = 0; j < 8; j++)
                    acc[i][j] = fmaf(a[i], b[j], acc[i][j]);
        }
        __syncthreads();
    }

#pragma unroll
    for (int i = 0; i < 8; i++) {
        int r = row0 + ty * 8 + i;
        if (r < N_NODES) {
#pragma unroll
            for (int j = 0; j < 8; j += 4) {
                float4 v;
                v.x = acc[i][j + 0];
                v.y = acc[i][j + 1];
                v.z = acc[i][j + 2];
                v.w = acc[i][j + 3];
                *reinterpret_cast<float4*>(out + (size_t)r * BN + tx * 8 + j) = v;
            }
        }
    }
}

__global__ void __launch_bounds__(256) gemm1_kernel(const float* __restrict__ X,
                                                    const float* __restrict__ W) {
    gemm_core<HID_C, IN_C>(X, W, g_bufA);
}
__global__ void __launch_bounds__(128) gemm2_kernel(const float* __restrict__ W) {
    gemm_core<OUT_C, HID_C>(g_h, W, g_z0s);
}

// ---------------- CSR aggregation, layer 1 (128 feats, warp/node) -----------
// h[i] = relu(dinv[i] * (dinv[i]*h0[i] + sum_s dinv[s]*h0[s]) + b1)
__global__ void __launch_bounds__(256) agg128_kernel(const float* __restrict__ b1) {
    const int lane = threadIdx.x & 31;
    const int node = (blockIdx.x * blockDim.x + threadIdx.x) >> 5;
    if (node >= N_NODES) return;
    const int beg = g_rowptr[node];
    const int end = g_rowptr[node + 1];
    const float4* __restrict__ H = reinterpret_cast<const float4*>(g_bufA);

    const float wn = g_dinv[node];
    float4 sv = H[(size_t)node * 32 + lane];
    float4 acc;
    acc.x = wn * sv.x; acc.y = wn * sv.y; acc.z = wn * sv.z; acc.w = wn * sv.w;

    int j = beg;
    for (; j + 7 < end; j += 8) {
        int   s[8];
        float w[8];
#pragma unroll
        for (int t = 0; t < 8; t++) s[t] = __ldg(&g_col[j + t]);
#pragma unroll
        for (int t = 0; t < 8; t++) w[t] = __ldg(&g_dinv[s[t]]);
#pragma unroll
        for (int t = 0; t < 8; t++) {
            float4 v = H[(size_t)s[t] * 32 + lane];
            acc.x = fmaf(w[t], v.x, acc.x);
            acc.y = fmaf(w[t], v.y, acc.y);
            acc.z = fmaf(w[t], v.z, acc.z);
            acc.w = fmaf(w[t], v.w, acc.w);
        }
    }
    for (; j < end; j++) {
        int s = __ldg(&g_col[j]);
        float w = __ldg(&g_dinv[s]);
        float4 v = H[(size_t)s * 32 + lane];
        acc.x = fmaf(w, v.x, acc.x);
        acc.y = fmaf(w, v.y, acc.y);
        acc.z = fmaf(w, v.z, acc.z);
        acc.w = fmaf(w, v.w, acc.w);
    }
    const float4 b = reinterpret_cast<const float4*>(b1)[lane];
    float4 r;
    r.x = fmaxf(fmaf(wn, acc.x, b.x), 0.f);
    r.y = fmaxf(fmaf(wn, acc.y, b.y), 0.f);
    r.z = fmaxf(fmaf(wn, acc.z, b.z), 0.f);
    r.w = fmaxf(fmaf(wn, acc.w, b.w), 0.f);
    reinterpret_cast<float4*>(g_h)[(size_t)node * 32 + lane] = r;
}

// ---------------- CSR aggregation, layer 2 (64 feats, 16 thr/node) ----------
__global__ void __launch_bounds__(256) agg64_kernel(const float* __restrict__ b2) {
    const int t0   = blockIdx.x * blockDim.x + threadIdx.x;
    const int l    = t0 & 15;
    const int node = t0 >> 4;
    if (node >= N_NODES) return;
    const int beg = g_rowptr[node];
    const int end = g_rowptr[node + 1];
    const float4* __restrict__ Z = reinterpret_cast<const float4*>(g_z0s);

    const float wn = g_dinv[node];
    float4 sv = Z[(size_t)node * 16 + l];
    float4 acc;
    acc.x = wn * sv.x; acc.y = wn * sv.y; acc.z = wn * sv.z; acc.w = wn * sv.w;

    int j = beg;
    for (; j + 7 < end; j += 8) {
        int   s[8];
        float w[8];
#pragma unroll
        for (int t = 0; t < 8; t++) s[t] = __ldg(&g_col[j + t]);
#pragma unroll
        for (int t = 0; t < 8; t++) w[t] = __ldg(&g_dinv[s[t]]);
#pragma unroll
        for (int t = 0; t < 8; t++) {
            float4 v = Z[(size_t)s[t] * 16 + l];
            acc.x = fmaf(w[t], v.x, acc.x);
            acc.y = fmaf(w[t], v.y, acc.y);
            acc.z = fmaf(w[t], v.z, acc.z);
            acc.w = fmaf(w[t], v.w, acc.w);
        }
    }
    for (; j < end; j++) {
        int s = __ldg(&g_col[j]);
        float w = __ldg(&g_dinv[s]);
        float4 v = Z[(size_t)s * 16 + l];
        acc.x = fmaf(w, v.x, acc.x);
        acc.y = fmaf(w, v.y, acc.y);
        acc.z = fmaf(w, v.z, acc.z);
        acc.w = fmaf(w, v.w, acc.w);
    }
    const float4 b = reinterpret_cast<const float4*>(b2)[l];
    float4 r;
    r.x = fmaf(wn, acc.x, b.x);
    r.y = fmaf(wn, acc.y, b.y);
    r.z = fmaf(wn, acc.z, b.z);
    r.w = fmaf(wn, acc.w, b.w);
    reinterpret_cast<float4*>(g_z)[(size_t)node * 16 + l] = r;
}

// ---------------- final: out[e] = dot(z[src], z[dst]) over 64 dims ----------
__global__ void edge_dot_kernel(const int* __restrict__ eli,
                                float* __restrict__ out) {
    const int lane = threadIdx.x & 31;
    const int warp = (blockIdx.x * blockDim.x + threadIdx.x) >> 5;
    if (warp >= N_LBL) return;
    int s = __ldg(&eli[warp]);
    int d = __ldg(&eli[N_LBL + warp]);
    float2 a = *reinterpret_cast<const float2*>(&g_z[(size_t)s * OUT_C + lane * 2]);
    float2 b = *reinterpret_cast<const float2*>(&g_z[(size_t)d * OUT_C + lane * 2]);
    float p = a.x * b.x + a.y * b.y;
#pragma unroll
    for (int o = 16; o > 0; o >>= 1) p += __shfl_xor_sync(0xffffffffu, p, o);
    if (lane == 0) out[warp] = p;
}

// ---------------- launch ----------------------------------------------------
extern "C" void kernel_launch(void* const* d_in, const int* in_sizes, int n_in,
                              void* d_out, int out_size) {
    const float* x   = (const float*)d_in[0];
    const int*   ei  = (const int*)d_in[1];   // int32 (JAX x64 disabled)
    const int*   eli = (const int*)d_in[2];
    const float* W1  = (const float*)d_in[3];
    const float* b1  = (const float*)d_in[4];
    const float* W2  = (const float*)d_in[5];
    const float* b2  = (const float*)d_in[6];
    float*       out = (float*)d_out;

    // Side stream for CSR build, forked/joined via events (valid under graph
    // capture; the fork makes CSR build concurrent with gemm1).
    cudaStream_t s2;
    cudaEvent_t  e0, e1;
    cudaStreamCreateWithFlags(&s2, cudaStreamNonBlocking);
    cudaEventCreateWithFlags(&e0, cudaEventDisableTiming);
    cudaEventCreateWithFlags(&e1, cudaEventDisableTiming);

    cudaEventRecord(e0, 0);
    cudaStreamWaitEvent(s2, e0, 0);
    // CSR build chain on s2 (independent of gemm1)
    zero_deg_kernel<<<(N_NODES + 255) / 256, 256, 0, s2>>>();
    deg_count_kernel<<<2048, 256, 0, s2>>>(ei);
    rowptr_kernel<<<1, SCAN_T, 0, s2>>>();
    fill_kernel<<<2048, 256, 0, s2>>>(ei);
    dinv_kernel<<<(N_NODES + 255) / 256, 256, 0, s2>>>();
    cudaEventRecord(e1, s2);

    // gemm1 on the main stream, concurrent with CSR build
    gemm1_kernel<<<(N_NODES + 127) / 128, 256>>>(x, W1);
    cudaStreamWaitEvent(0, e1, 0);   // join before aggregation

    agg128_kernel<<<(N_NODES * 32 + 255) / 256, 256>>>(b1);
    gemm2_kernel<<<(N_NODES + 127) / 128, 128>>>(W2);
    agg64_kernel<<<(N_NODES * 16 + 255) / 256, 256>>>(b2);
    edge_dot_kernel<<<(N_LBL * 32 + 255) / 256, 256>>>(eli, out);
}

// round 8
// speedup vs baseline: 2.2390x; 1.4947x over previous
#include <cuda_runtime.h>
#include <cstdint>
#include <cstddef>

// ---------------- problem constants ----------------
constexpr int N_NODES = 100000;
constexpr int IN_C    = 256;
constexpr int HID_C   = 128;
constexpr int OUT_C   = 64;
constexpr int N_EDGES = 1600000;
constexpr int N_LBL   = 200000;

// ---------------- scratch (device globals) ----------------------------------
__device__ __align__(16) int   g_deg   [N_NODES];
__device__ __align__(16) int   g_rowptr[N_NODES + 1];
__device__ __align__(16) int   g_cursor[N_NODES];
__device__ __align__(16) int   g_col   [N_EDGES];
__device__ __align__(16) float g_dinv  [N_NODES];
__device__ __align__(16) float g_bufA[(size_t)N_NODES * HID_C]; // h0s = (x@W1)*dinv
__device__ __align__(16) float g_h   [(size_t)N_NODES * HID_C]; // h (post layer 1)
__device__ __align__(16) float g_z0s [(size_t)N_NODES * OUT_C]; // (h@W2)*dinv
__device__ __align__(16) float g_z   [(size_t)N_NODES * OUT_C]; // final node embeddings

// ---------------- CSR build --------------------------------------------------
__global__ void zero_deg_kernel() {
    const int i = blockIdx.x * blockDim.x + threadIdx.x;
    if (i < N_NODES) g_deg[i] = 0;
}

__global__ void deg_count_kernel(const int* __restrict__ ei) {
    const int idx    = blockIdx.x * blockDim.x + threadIdx.x;
    const int stride = gridDim.x * blockDim.x;
    for (int e = idx; e < N_EDGES; e += stride)
        atomicAdd(&g_deg[__ldg(&ei[N_EDGES + e])], 1);
}

constexpr int SCAN_T  = 1024;
constexpr int SCAN_CH = (N_NODES + SCAN_T - 1) / SCAN_T;   // 98

__global__ void rowptr_kernel() {
    __shared__ int part[SCAN_T];
    const int t    = threadIdx.x;
    const int base = t * SCAN_CH;
    int sum = 0;
    for (int i = 0; i < SCAN_CH; i++) {
        int idx = base + i;
        if (idx < N_NODES) sum += g_deg[idx];
    }
    part[t] = sum;
    __syncthreads();
#pragma unroll
    for (int off = 1; off < SCAN_T; off <<= 1) {
        int v = (t >= off) ? part[t - off] : 0;
        __syncthreads();
        part[t] += v;
        __syncthreads();
    }
    int run = part[t] - sum;
    for (int i = 0; i < SCAN_CH; i++) {
        int idx = base + i;
        if (idx < N_NODES) {
            g_rowptr[idx] = run;
            g_cursor[idx] = run;
            run += g_deg[idx];
        }
    }
    if (t == 0) g_rowptr[N_NODES] = part[SCAN_T - 1];
}

__global__ void fill_kernel(const int* __restrict__ ei) {
    const int idx    = blockIdx.x * blockDim.x + threadIdx.x;
    const int stride = gridDim.x * blockDim.x;
    for (int e = idx; e < N_EDGES; e += stride) {
        int s = __ldg(&ei[e]);
        int d = __ldg(&ei[N_EDGES + e]);
        int pos = atomicAdd(&g_cursor[d], 1);
        g_col[pos] = s;
    }
}

__global__ void dinv_kernel() {
    const int i = blockIdx.x * blockDim.x + threadIdx.x;
    if (i < N_NODES) g_dinv[i] = rsqrtf((float)g_deg[i] + 1.0f);  // +1 self-loop
}

// ---------------- double-buffered fp32 GEMM, dinv-scaled epilogue -----------
// out[r,:] = dinv[r] * (X[r,:] @ W).  BM=128, BK=16, 8x8 regs/thread.
// Two-stage pipeline: register-prefetch next tile during compute, STS to the
// alternate smem buffer, one barrier per k-tile.
template <int BN, int K>
__device__ __forceinline__ void gemm_core(const float* __restrict__ X,
                                          const float* __restrict__ W,
                                          float* __restrict__ out) {
    constexpr int BM  = 128, BK = 16;
    constexpr int TX  = BN / 8;
    constexpr int NT  = 16 * TX;
    constexpr int XLD = BM * BK / NT / 4;   // float4 per thread (X tile)
    constexpr int WLD = BK * BN / NT / 4;   // float4 per thread (W tile)
    constexpr int NTILE = K / BK;

    __shared__ float xs[2][BK][BM];
    __shared__ float ws[2][BK][BN];

    const int tid  = threadIdx.x;
    const int tx   = tid % TX;
    const int ty   = tid / TX;
    const int row0 = blockIdx.x * BM;

    float4 xreg[XLD], wreg[WLD];

    auto load_tile = [&](int k0) {
#pragma unroll
        for (int i = 0; i < XLD; i++) {
            int f = tid + i * NT;
            int r = f >> 2, kq = f & 3;
            int gr = row0 + r;
            if (gr > N_NODES - 1) gr = N_NODES - 1;   // clamp; dup row discarded
            xreg[i] = *reinterpret_cast<const float4*>(X + (size_t)gr * K + k0 + kq * 4);
        }
#pragma unroll
        for (int i = 0; i < WLD; i++) {
            int f  = tid + i * NT;
            int kr = f / (BN / 4), cq = f % (BN / 4);
            wreg[i] = *reinterpret_cast<const float4*>(W + (size_t)(k0 + kr) * BN + cq * 4);
        }
    };
    auto store_tile = [&](int buf) {
#pragma unroll
        for (int i = 0; i < XLD; i++) {
            int f = tid + i * NT;
            int r = f >> 2, kq = f & 3;
            xs[buf][kq * 4 + 0][r] = xreg[i].x;
            xs[buf][kq * 4 + 1][r] = xreg[i].y;
            xs[buf][kq * 4 + 2][r] = xreg[i].z;
            xs[buf][kq * 4 + 3][r] = xreg[i].w;
        }
#pragma unroll
        for (int i = 0; i < WLD; i++) {
            int f  = tid + i * NT;
            int kr = f / (BN / 4), cq = f % (BN / 4);
            *reinterpret_cast<float4*>(&ws[buf][kr][cq * 4]) = wreg[i];
        }
    };

    float acc[8][8];
#pragma unroll
    for (int i = 0; i < 8; i++)
#pragma unroll
        for (int j = 0; j < 8; j++) acc[i][j] = 0.f;

    load_tile(0);
    store_tile(0);
    __syncthreads();

    for (int t = 0; t < NTILE; t++) {
        const int cur = t & 1;
        if (t + 1 < NTILE) load_tile((t + 1) * BK);   // prefetch into regs

#pragma unroll
        for (int kk = 0; kk < BK; kk++) {
            float a[8], b[8];
            *reinterpret_cast<float4*>(a)     = *reinterpret_cast<const float4*>(&xs[cur][kk][ty * 8]);
            *reinterpret_cast<float4*>(a + 4) = *reinterpret_cast<const float4*>(&xs[cur][kk][ty * 8 + 4]);
            *reinterpret_cast<float4*>(b)     = *reinterpret_cast<const float4*>(&ws[cur][kk][tx * 8]);
            *reinterpret_cast<float4*>(b + 4) = *reinterpret_cast<const float4*>(&ws[cur][kk][tx * 8 + 4]);
#pragma unroll
            for (int i = 0; i < 8; i++)
#pragma unroll
                for (int j = 0; j < 8; j++)
                    acc[i][j] = fmaf(a[i], b[j], acc[i][j]);
        }
        if (t + 1 < NTILE) {
            store_tile((t + 1) & 1);
            __syncthreads();
        }
    }

#pragma unroll
    for (int i = 0; i < 8; i++) {
        int r = row0 + ty * 8 + i;
        if (r < N_NODES) {
            float s = g_dinv[r];
#pragma unroll
            for (int j = 0; j < 8; j += 4) {
                float4 v;
                v.x = acc[i][j + 0] * s;
                v.y = acc[i][j + 1] * s;
                v.z = acc[i][j + 2] * s;
                v.w = acc[i][j + 3] * s;
                *reinterpret_cast<float4*>(out + (size_t)r * BN + tx * 8 + j) = v;
            }
        }
    }
}

__global__ void __launch_bounds__(256, 2) gemm1_kernel(const float* __restrict__ X,
                                                       const float* __restrict__ W) {
    gemm_core<HID_C, IN_C>(X, W, g_bufA);
}
__global__ void __launch_bounds__(128, 4) gemm2_kernel(const float* __restrict__ W) {
    gemm_core<OUT_C, HID_C>(g_h, W, g_z0s);
}

// ---------------- CSR aggregation, layer 1 (128 feats, warp/node) -----------
// h[i] = relu(dinv[i] * (h0s[i] + sum_{s in N(i)} h0s[s]) + b1)   [h0s pre-scaled]
__global__ void __launch_bounds__(256) agg128_kernel(const float* __restrict__ b1) {
    const int lane = threadIdx.x & 31;
    const int node = (blockIdx.x * blockDim.x + threadIdx.x) >> 5;
    if (node >= N_NODES) return;
    const int beg = g_rowptr[node];
    const int end = g_rowptr[node + 1];
    const float4* __restrict__ H = reinterpret_cast<const float4*>(g_bufA);

    float4 acc = H[(size_t)node * 32 + lane];   // self-loop (already dinv-scaled)
    int j = beg;
    for (; j + 7 < end; j += 8) {
        int s[8];
#pragma unroll
        for (int t = 0; t < 8; t++) s[t] = __ldg(&g_col[j + t]);
#pragma unroll
        for (int t = 0; t < 8; t++) {
            float4 v = H[(size_t)s[t] * 32 + lane];
            acc.x += v.x; acc.y += v.y; acc.z += v.z; acc.w += v.w;
        }
    }
    for (; j < end; j++) {
        int s = __ldg(&g_col[j]);
        float4 v = H[(size_t)s * 32 + lane];
        acc.x += v.x; acc.y += v.y; acc.z += v.z; acc.w += v.w;
    }
    const float sc = g_dinv[node];
    const float4 b = reinterpret_cast<const float4*>(b1)[lane];
    float4 r;
    r.x = fmaxf(fmaf(sc, acc.x, b.x), 0.f);
    r.y = fmaxf(fmaf(sc, acc.y, b.y), 0.f);
    r.z = fmaxf(fmaf(sc, acc.z, b.z), 0.f);
    r.w = fmaxf(fmaf(sc, acc.w, b.w), 0.f);
    reinterpret_cast<float4*>(g_h)[(size_t)node * 32 + lane] = r;
}

// ---------------- CSR aggregation, layer 2 (64 feats, 16 thr/node) ----------
__global__ void __launch_bounds__(256) agg64_kernel(const float* __restrict__ b2) {
    const int t0   = blockIdx.x * blockDim.x + threadIdx.x;
    const int l    = t0 & 15;
    const int node = t0 >> 4;
    if (node >= N_NODES) return;
    const int beg = g_rowptr[node];
    const int end = g_rowptr[node + 1];
    const float4* __restrict__ Z = reinterpret_cast<const float4*>(g_z0s);

    float4 acc = Z[(size_t)node * 16 + l];
    int j = beg;
    for (; j + 7 < end; j += 8) {
        int s[8];
#pragma unroll
        for (int t = 0; t < 8; t++) s[t] = __ldg(&g_col[j + t]);
#pragma unroll
        for (int t = 0; t < 8; t++) {
            float4 v = Z[(size_t)s[t] * 16 + l];
            acc.x += v.x; acc.y += v.y; acc.z += v.z; acc.w += v.w;
        }
    }
    for (; j < end; j++) {
        int s = __ldg(&g_col[j]);
        float4 v = Z[(size_t)s * 16 + l];
        acc.x += v.x; acc.y += v.y; acc.z += v.z; acc.w += v.w;
    }
    const float sc = g_dinv[node];
    const float4 b = reinterpret_cast<const float4*>(b2)[l];
    float4 r;
    r.x = fmaf(sc, acc.x, b.x);
    r.y = fmaf(sc, acc.y, b.y);
    r.z = fmaf(sc, acc.z, b.z);
    r.w = fmaf(sc, acc.w, b.w);
    reinterpret_cast<float4*>(g_z)[(size_t)node * 16 + l] = r;
}

// ---------------- final: out[e] = dot(z[src], z[dst]) over 64 dims ----------
__global__ void edge_dot_kernel(const int* __restrict__ eli,
                                float* __restrict__ out) {
    const int lane = threadIdx.x & 31;
    const int warp = (blockIdx.x * blockDim.x + threadIdx.x) >> 5;
    if (warp >= N_LBL) return;
    int s = __ldg(&eli[warp]);
    int d = __ldg(&eli[N_LBL + warp]);
    float2 a = *reinterpret_cast<const float2*>(&g_z[(size_t)s * OUT_C + lane * 2]);
    float2 b = *reinterpret_cast<const float2*>(&g_z[(size_t)d * OUT_C + lane * 2]);
    float p = a.x * b.x + a.y * b.y;
#pragma unroll
    for (int o = 16; o > 0; o >>= 1) p += __shfl_xor_sync(0xffffffffu, p, o);
    if (lane == 0) out[warp] = p;
}

// ---------------- launch ----------------------------------------------------
extern "C" void kernel_launch(void* const* d_in, const int* in_sizes, int n_in,
                              void* d_out, int out_size) {
    const float* x   = (const float*)d_in[0];
    const int*   ei  = (const int*)d_in[1];   // int32 (JAX x64 disabled)
    const int*   eli = (const int*)d_in[2];
    const float* W1  = (const float*)d_in[3];
    const float* b1  = (const float*)d_in[4];
    const float* W2  = (const float*)d_in[5];
    const float* b2  = (const float*)d_in[6];
    float*       out = (float*)d_out;

    cudaStream_t s2;
    cudaEvent_t  eA, eB;
    cudaStreamCreateWithFlags(&s2, cudaStreamNonBlocking);
    cudaEventCreateWithFlags(&eA, cudaEventDisableTiming);
    cudaEventCreateWithFlags(&eB, cudaEventDisableTiming);

    // main: degree (needed by both dinv and rowptr)
    zero_deg_kernel<<<(N_NODES + 255) / 256, 256>>>();
    deg_count_kernel<<<2048, 256>>>(ei);
    cudaEventRecord(eA, 0);

    // side: rowptr + fill, concurrent with dinv + gemm1
    cudaStreamWaitEvent(s2, eA, 0);
    rowptr_kernel<<<1, SCAN_T, 0, s2>>>();
    fill_kernel<<<2048, 256, 0, s2>>>(ei);
    cudaEventRecord(eB, s2);

    // main: dinv -> gemm1 (scaled epilogue)
    dinv_kernel<<<(N_NODES + 255) / 256, 256>>>();
    gemm1_kernel<<<(N_NODES + 127) / 128, 256>>>(x, W1);
    cudaStreamWaitEvent(0, eB, 0);   // join CSR before aggregation

    agg128_kernel<<<(N_NODES * 32 + 255) / 256, 256>>>(b1);
    gemm2_kernel<<<(N_NODES + 127) / 128, 128>>>(W2);
    agg64_kernel<<<(N_NODES * 16 + 255) / 256, 256>>>(b2);
    edge_dot_kernel<<<(N_LBL * 32 + 255) / 256, 256>>>(eli, out);
}